// round 15
// baseline (speedup 1.0000x reference)
#include <cuda_runtime.h>

#define LBL   64
#define MAXT  200000
#define S_CH  500
#define MAXK  512

// scratch (static device globals — no allocation)
__device__ float         g_v[(size_t)MAXT * LBL];   // g_v[t] = V[t+1] (v AFTER step t)
__device__ unsigned char g_bp[(size_t)MAXT * LBL];  // bp rows, row 0 unused
__device__ unsigned char g_H[MAXK * LBL];           // per-chunk composed maps
__device__ int           g_E[MAXK + 2];             // boundary path values
__device__ int           g_best;

// ---------------------------------------------------------------------------
// Phase 1: serial forward pass. 1 block, 128 threads (4 warps, 1 per SMSP).
// warp w handles tags n = 16w..16w+15; 2 lanes per tag (q=0,1), 32 prevs/lane.
// v row layout (176 floats):
//   [0..63]    primary v[0..63]
//   [80..111]  park slots (written by q=1 lanes of tags 0..31, never read)
//   [144..175] REPLICA of v[32..63], natural order (read by q=1)
// LDS (per chunk j): q=0 -> bank quad j, q=1 -> quad (4+j)&7 => disjoint,
// 1 wavefront per LDS.128. STS per warp hits 32 distinct banks => 1 wavefront.
// Chain: LDS -> add/max tree -> +feat -> 1 SHFL -> FMNMX -> STS -> BAR(nw=4).
// Emission folded pre-shuffle (bit-exact: fmax(a+f,b+f)==fmax(a,b)+f, monotone
// rounding). Step loop unroll 8 (R13/R14 wins; R5's 60KB full unroll was
// fatal — do not expand further).
// R15 change (single variable): the q=1 off-chain STG of vn moved from
// BEFORE the barrier to AFTER it — removes ~5 issue cyc from the barrier-
// arrival path of q=1 warps; the STG now issues inside the next step's
// LDS-latency shadow. vn is in a register; no ordering with the barrier is
// needed (g_v is only read by later kernels). Body otherwise IDENTICAL to
// the 21.07ms R14 kernel (R5-R8, R12: batching / pipelining / packed-math /
// smem-history all regressed — do not reapply).
// ---------------------------------------------------------------------------
__global__ void __launch_bounds__(128, 1)
fwd_kernel(const float* __restrict__ feats, const float* __restrict__ trans, int T)
{
    __shared__ __align__(16) float sv[2][176];
    __shared__ __align__(16) float fsh[2][64 * LBL];   // 2 x 16KB feat chunks

    const int tid  = threadIdx.x;
    const int w    = tid >> 5;
    const int lane = tid & 31;
    const int k    = lane >> 1;       // tag within warp (0..15)
    const int q    = lane & 1;        // prev-half (0: v[0..31], 1: v[32..63] via replica)
    const int n    = w * 16 + k;

    // transition segment T[n][q*32 .. q*32+31] (natural order)
    const float4* trr = reinterpret_cast<const float4*>(trans + n * 64 + q * 32);
    const float4 t0 = trr[0], t1 = trr[1], t2 = trr[2], t3 = trr[3];
    const float4 t4 = trr[4], t5 = trr[5], t6 = trr[6], t7 = trr[7];

    // init primary [0..63] and replica [144..175] (parks never read)
    if (tid < 64) {
        sv[0][tid] = (tid == 62) ? 0.0f : -10000.0f;           // START=62
    } else if (tid < 96) {
        sv[0][tid + 80] = ((tid - 32) == 62) ? 0.0f : -10000.0f; // replica of v[32..63]
    }

    const int nch = (T + 63) >> 6;
    const int totElems = T * LBL;
    const int rbase = q ? 144 : 0;                  // per-lane read base (floats)
    const int sbase = q ? ((n < 32) ? (80 + n) : (112 + n)) : n;  // store slot

    // prefetch one 16KB chunk (64 steps) with cp.async
    auto prefetch = [&](int ch, int buf) {
        const float* src = feats + ch * 4096;
#pragma unroll
        for (int i = 0; i < 8; i++) {
            int e = tid + i * 128;                 // 16B units within chunk
            if (ch * 4096 + e * 4 + 3 < totElems) {
                unsigned saddr = (unsigned)__cvta_generic_to_shared(&fsh[buf][e * 4]);
                asm volatile("cp.async.cg.shared.global [%0], [%1], 16;"
                             :: "r"(saddr), "l"(src + e * 4));
            }
        }
        asm volatile("cp.async.commit_group;" ::: "memory");
    };

    prefetch(0, 0);
    if (nch > 1) prefetch(1, 1); else asm volatile("cp.async.commit_group;" ::: "memory");
    __syncthreads();

    for (int ch = 0; ch < nch; ch++) {
        asm volatile("cp.async.wait_group 1;" ::: "memory");
        __syncthreads();
        const float* fb  = fsh[ch & 1] + n;                      // imm offsets below
        float*       gvp = g_v + (size_t)(ch << 6) * LBL + n;    // imm offsets below
        const int steps = min(64, T - (ch << 6));
#pragma unroll 8
        for (int i = 0; i < steps; i++) {
            const int cur = i & 1;  // compile-time under unroll-8
            const float4* vv = reinterpret_cast<const float4*>(&sv[cur][rbase]);
            const float4 a0 = vv[0], a1 = vv[1], a2 = vv[2], a3 = vv[3];
            const float4 a4 = vv[4], a5 = vv[5], a6 = vv[6], a7 = vv[7];
            float m0 = fmaxf(fmaxf(a0.x + t0.x, a0.y + t0.y), fmaxf(a0.z + t0.z, a0.w + t0.w));
            float m1 = fmaxf(fmaxf(a1.x + t1.x, a1.y + t1.y), fmaxf(a1.z + t1.z, a1.w + t1.w));
            float m2 = fmaxf(fmaxf(a2.x + t2.x, a2.y + t2.y), fmaxf(a2.z + t2.z, a2.w + t2.w));
            float m3 = fmaxf(fmaxf(a3.x + t3.x, a3.y + t3.y), fmaxf(a3.z + t3.z, a3.w + t3.w));
            float m4 = fmaxf(fmaxf(a4.x + t4.x, a4.y + t4.y), fmaxf(a4.z + t4.z, a4.w + t4.w));
            float m5 = fmaxf(fmaxf(a5.x + t5.x, a5.y + t5.y), fmaxf(a5.z + t5.z, a5.w + t5.w));
            float m6 = fmaxf(fmaxf(a6.x + t6.x, a6.y + t6.y), fmaxf(a6.z + t6.z, a6.w + t6.w));
            float m7 = fmaxf(fmaxf(a7.x + t7.x, a7.y + t7.y), fmaxf(a7.z + t7.z, a7.w + t7.w));
            float mm = fmaxf(fmaxf(fmaxf(m0, m1), fmaxf(m2, m3)),
                             fmaxf(fmaxf(m4, m5), fmaxf(m6, m7)));
            // fold emission before the shuffle (bit-exact, see header comment)
            mm += fb[i << 6];
            const float other = __shfl_xor_sync(0xffffffffu, mm, 1);
            const float vn = fmaxf(mm, other);
            sv[cur ^ 1][sbase] = vn;           // chain store (primary/park/replica)
            __syncthreads();
            if (q == 1) gvp[i * LBL] = vn;     // off-chain store, post-barrier:
                                               // issues in next step's LDS shadow
        }
        if (ch + 2 < nch) prefetch(ch + 2, ch & 1);
        else asm volatile("cp.async.commit_group;" ::: "memory");
    }
}

// ---------------------------------------------------------------------------
// Phase 2: recompute backpointers for all t in [1, T-1], fully parallel.
// block handles 16 consecutive t (4 at a time); thread = (tt, n). Strict '>'
// ascending p == jnp.argmax first-index tie-break. Bit-exact adds.
// ---------------------------------------------------------------------------
__global__ void __launch_bounds__(256)
bp_kernel(const float* __restrict__ trans, int T)
{
    __shared__ float trsT[64 * 65];   // transposed + padded: trsT[p*65+n]
    __shared__ float vsh[4][64];

    const int tid = threadIdx.x;
    for (int x = tid; x < 4096; x += 256) {
        int nn = x >> 6, pp = x & 63;
        trsT[pp * 65 + nn] = trans[x];
    }
    const int base_t = 1 + blockIdx.x * 16;
    const int tt = tid >> 6, n = tid & 63;

    for (int r = 0; r < 4; r++) {
        const int t = base_t + r * 4 + tt;
        __syncthreads();
        if (t <= T - 1) vsh[tt][n] = g_v[(size_t)(t - 1) * LBL + n];  // = V[t]
        __syncthreads();
        if (t > T - 1) continue;

        float m = -3.4e38f;
        int bi = 0;
#pragma unroll 8
        for (int p = 0; p < 64; p++) {
            float s = vsh[tt][p] + trsT[p * 65 + n];
            if (s > m) { m = s; bi = p; }
        }
        g_bp[(size_t)t * LBL + n] = (unsigned char)bi;
    }
}

// ---------------------------------------------------------------------------
// Phase 3a: per-chunk composed backpointer maps (64-entry byte maps).
// ---------------------------------------------------------------------------
__global__ void __launch_bounds__(64)
maps_kernel(int T, int K)
{
    __shared__ unsigned char sbp[S_CH * LBL];
    const int c = blockIdx.x, tid = threadIdx.x;
    const int lo = c * S_CH + 1;
    const int hi = min((c + 1) * S_CH, T - 1);
    const int nrows = hi - lo + 1;

    const uint4* src = reinterpret_cast<const uint4*>(g_bp + (size_t)lo * LBL);
    uint4* dst = reinterpret_cast<uint4*>(sbp);
    for (int i = tid; i < nrows * 4; i += 64) dst[i] = src[i];
    __syncthreads();

    int m = tid;
    for (int j = nrows - 1; j >= 0; j--) m = sbp[j * LBL + m];
    g_H[c * LBL + tid] = (unsigned char)m;
}

// ---------------------------------------------------------------------------
// Phase 3b: terminal argmax + score, then serial chase over K chunk maps.
// ---------------------------------------------------------------------------
__global__ void __launch_bounds__(64)
chase_kernel(const float* __restrict__ trans, int T, int K,
             float* __restrict__ out, int out_size)
{
    __shared__ unsigned char sh[MAXK * LBL];
    const int tid = threadIdx.x;
    for (int i = tid; i < K * 4; i += 64)
        reinterpret_cast<uint4*>(sh)[i] = reinterpret_cast<const uint4*>(g_H)[i];
    __syncthreads();

    if (tid == 0) {
        // terminal = V[T] + transitions[STOP]; STOP = 63
        float m = -3.4e38f; int best = 0;
        for (int p = 0; p < 64; p++) {
            float s = g_v[(size_t)(T - 1) * LBL + p] + trans[63 * 64 + p];
            if (s > m) { m = s; best = p; }
        }
        if (out_size > T) out[0] = m;   // path_score
        g_best = best;
        int e = best;                   // = path[T-1]
        for (int c = K - 1; c >= 1; c--) {
            e = sh[c * LBL + e];        // -> path[c*S]
            g_E[c] = e;
        }
    }
}

// ---------------------------------------------------------------------------
// Phase 3c: parallel fill. Chunk c writes path[j] for j in [c*S, hi).
// ---------------------------------------------------------------------------
__global__ void __launch_bounds__(64)
fill_kernel(int T, int K, float* __restrict__ out, int base)
{
    __shared__ unsigned char sbp[S_CH * LBL];
    const int c = blockIdx.x, tid = threadIdx.x;
    const int lo = c * S_CH + 1;
    const int hi = min((c + 1) * S_CH, T - 1);
    const int nrows = hi - lo + 1;

    const uint4* src = reinterpret_cast<const uint4*>(g_bp + (size_t)lo * LBL);
    uint4* dst = reinterpret_cast<uint4*>(sbp);
    for (int i = tid; i < nrows * 4; i += 64) dst[i] = src[i];
    __syncthreads();

    if (tid == 0) {
        int j, cur;
        if (c == K - 1) {
            cur = g_best;                       // path[T-1]
            out[base + T - 1] = (float)cur;
            j = T - 2;
        } else {
            const int x = g_E[c + 1];           // path[(c+1)*S]
            cur = sbp[(hi - lo) * LBL + x];     // bp[(c+1)*S][x] = path[hi-1]
            out[base + hi - 1] = (float)cur;
            j = hi - 2;
        }
        for (; j >= c * S_CH; j--) {
            cur = sbp[(j + 1 - lo) * LBL + cur];
            out[base + j] = (float)cur;
        }
    }
}

// ---------------------------------------------------------------------------
extern "C" void kernel_launch(void* const* d_in, const int* in_sizes, int n_in,
                              void* d_out, int out_size)
{
    const float* feats = (const float*)d_in[0];   // (1, T, 64) float32
    const float* trans = (const float*)d_in[1];   // (64, 64) float32
    float* out = (float*)d_out;

    const int T = in_sizes[0] / LBL;
    const int K = (T + S_CH - 1) / S_CH;
    const int base = (out_size > T) ? 1 : 0;

    fwd_kernel<<<1, 128>>>(feats, trans, T);

    const int nb = (T - 1 + 15) / 16;
    bp_kernel<<<nb, 256>>>(trans, T);

    maps_kernel<<<K, 64>>>(T, K);
    chase_kernel<<<1, 64>>>(trans, T, K, out, out_size);
    fill_kernel<<<K, 64>>>(T, K, out, base);
}

// round 16
// speedup vs baseline: 1.0008x; 1.0008x over previous
#include <cuda_runtime.h>

#define LBL   64
#define MAXT  200000
#define S_CH  500
#define MAXK  512

// scratch (static device globals — no allocation)
__device__ float         g_v[(size_t)MAXT * LBL];   // g_v[t] = V[t+1] (v AFTER step t)
__device__ unsigned char g_bp[(size_t)MAXT * LBL];  // bp rows, row 0 unused
__device__ unsigned char g_H[MAXK * LBL];           // per-chunk composed maps
__device__ int           g_E[MAXK + 2];             // boundary path values
__device__ int           g_best;

// ---------------------------------------------------------------------------
// FINAL (== R14, best measured: 21073.7us). Serial Viterbi forward pass.
// 1 block, 128 threads (4 warps, 1 per SMSP). warp w handles tags
// n = 16w..16w+15; 2 lanes per tag (q=0,1), 32 prevs/lane.
// v row layout (176 floats):
//   [0..63]    primary v[0..63]
//   [80..111]  park slots (written by q=1 lanes of tags 0..31, never read)
//   [144..175] REPLICA of v[32..63], natural order (read by q=1)
// LDS (per chunk j): q=0 -> bank quad j, q=1 -> quad (4+j)&7 => disjoint,
// 1 wavefront per LDS.128 (this layout fix was the -5.8ms win of R10).
// STS per warp hits 32 distinct banks => 1 wavefront.
// Chain: LDS -> add/max tree -> +feat -> 1 SHFL -> FMNMX -> STS -> BAR(nw=4,
// defer-blocking). Emission folded pre-shuffle (bit-exact:
// fmax(a+f,b+f)==fmax(a,b)+f, monotone rounding). Step loop unroll 8.
// Tested-and-rejected (do not reapply): full-64 unroll (I$ throttle, R5),
// feat pipelining / batched float4 g_v stores (R6), add.rn.f32x2 (R7),
// dual-copy-v pointer web (R8), smem v-history + bulk copy-out (R12),
// post-barrier STG (R15, neutral — barrier is defer-blocking anyway).
// ---------------------------------------------------------------------------
__global__ void __launch_bounds__(128, 1)
fwd_kernel(const float* __restrict__ feats, const float* __restrict__ trans, int T)
{
    __shared__ __align__(16) float sv[2][176];
    __shared__ __align__(16) float fsh[2][64 * LBL];   // 2 x 16KB feat chunks

    const int tid  = threadIdx.x;
    const int w    = tid >> 5;
    const int lane = tid & 31;
    const int k    = lane >> 1;       // tag within warp (0..15)
    const int q    = lane & 1;        // prev-half (0: v[0..31], 1: v[32..63] via replica)
    const int n    = w * 16 + k;

    // transition segment T[n][q*32 .. q*32+31] (natural order)
    const float4* trr = reinterpret_cast<const float4*>(trans + n * 64 + q * 32);
    const float4 t0 = trr[0], t1 = trr[1], t2 = trr[2], t3 = trr[3];
    const float4 t4 = trr[4], t5 = trr[5], t6 = trr[6], t7 = trr[7];

    // init primary [0..63] and replica [144..175] (parks never read)
    if (tid < 64) {
        sv[0][tid] = (tid == 62) ? 0.0f : -10000.0f;           // START=62
    } else if (tid < 96) {
        sv[0][tid + 80] = ((tid - 32) == 62) ? 0.0f : -10000.0f; // replica of v[32..63]
    }

    const int nch = (T + 63) >> 6;
    const int totElems = T * LBL;
    const int rbase = q ? 144 : 0;                  // per-lane read base (floats)
    const int sbase = q ? ((n < 32) ? (80 + n) : (112 + n)) : n;  // store slot

    // prefetch one 16KB chunk (64 steps) with cp.async
    auto prefetch = [&](int ch, int buf) {
        const float* src = feats + ch * 4096;
#pragma unroll
        for (int i = 0; i < 8; i++) {
            int e = tid + i * 128;                 // 16B units within chunk
            if (ch * 4096 + e * 4 + 3 < totElems) {
                unsigned saddr = (unsigned)__cvta_generic_to_shared(&fsh[buf][e * 4]);
                asm volatile("cp.async.cg.shared.global [%0], [%1], 16;"
                             :: "r"(saddr), "l"(src + e * 4));
            }
        }
        asm volatile("cp.async.commit_group;" ::: "memory");
    };

    prefetch(0, 0);
    if (nch > 1) prefetch(1, 1); else asm volatile("cp.async.commit_group;" ::: "memory");
    __syncthreads();

    for (int ch = 0; ch < nch; ch++) {
        asm volatile("cp.async.wait_group 1;" ::: "memory");
        __syncthreads();
        const float* fb  = fsh[ch & 1] + n;                      // imm offsets below
        float*       gvp = g_v + (size_t)(ch << 6) * LBL + n;    // imm offsets below
        const int steps = min(64, T - (ch << 6));
#pragma unroll 8
        for (int i = 0; i < steps; i++) {
            const int cur = i & 1;  // compile-time under unroll-8
            const float4* vv = reinterpret_cast<const float4*>(&sv[cur][rbase]);
            const float4 a0 = vv[0], a1 = vv[1], a2 = vv[2], a3 = vv[3];
            const float4 a4 = vv[4], a5 = vv[5], a6 = vv[6], a7 = vv[7];
            float m0 = fmaxf(fmaxf(a0.x + t0.x, a0.y + t0.y), fmaxf(a0.z + t0.z, a0.w + t0.w));
            float m1 = fmaxf(fmaxf(a1.x + t1.x, a1.y + t1.y), fmaxf(a1.z + t1.z, a1.w + t1.w));
            float m2 = fmaxf(fmaxf(a2.x + t2.x, a2.y + t2.y), fmaxf(a2.z + t2.z, a2.w + t2.w));
            float m3 = fmaxf(fmaxf(a3.x + t3.x, a3.y + t3.y), fmaxf(a3.z + t3.z, a3.w + t3.w));
            float m4 = fmaxf(fmaxf(a4.x + t4.x, a4.y + t4.y), fmaxf(a4.z + t4.z, a4.w + t4.w));
            float m5 = fmaxf(fmaxf(a5.x + t5.x, a5.y + t5.y), fmaxf(a5.z + t5.z, a5.w + t5.w));
            float m6 = fmaxf(fmaxf(a6.x + t6.x, a6.y + t6.y), fmaxf(a6.z + t6.z, a6.w + t6.w));
            float m7 = fmaxf(fmaxf(a7.x + t7.x, a7.y + t7.y), fmaxf(a7.z + t7.z, a7.w + t7.w));
            float mm = fmaxf(fmaxf(fmaxf(m0, m1), fmaxf(m2, m3)),
                             fmaxf(fmaxf(m4, m5), fmaxf(m6, m7)));
            // fold emission before the shuffle (bit-exact, see header comment)
            mm += fb[i << 6];
            const float other = __shfl_xor_sync(0xffffffffu, mm, 1);
            const float vn = fmaxf(mm, other);
            sv[cur ^ 1][sbase] = vn;           // chain store (primary/park/replica)
            if (q == 1) gvp[i * LBL] = vn;     // off-chain store (global)
            __syncthreads();
        }
        if (ch + 2 < nch) prefetch(ch + 2, ch & 1);
        else asm volatile("cp.async.commit_group;" ::: "memory");
    }
}

// ---------------------------------------------------------------------------
// Phase 2: recompute backpointers for all t in [1, T-1], fully parallel.
// block handles 16 consecutive t (4 at a time); thread = (tt, n). Strict '>'
// ascending p == jnp.argmax first-index tie-break. Bit-exact adds.
// ---------------------------------------------------------------------------
__global__ void __launch_bounds__(256)
bp_kernel(const float* __restrict__ trans, int T)
{
    __shared__ float trsT[64 * 65];   // transposed + padded: trsT[p*65+n]
    __shared__ float vsh[4][64];

    const int tid = threadIdx.x;
    for (int x = tid; x < 4096; x += 256) {
        int nn = x >> 6, pp = x & 63;
        trsT[pp * 65 + nn] = trans[x];
    }
    const int base_t = 1 + blockIdx.x * 16;
    const int tt = tid >> 6, n = tid & 63;

    for (int r = 0; r < 4; r++) {
        const int t = base_t + r * 4 + tt;
        __syncthreads();
        if (t <= T - 1) vsh[tt][n] = g_v[(size_t)(t - 1) * LBL + n];  // = V[t]
        __syncthreads();
        if (t > T - 1) continue;

        float m = -3.4e38f;
        int bi = 0;
#pragma unroll 8
        for (int p = 0; p < 64; p++) {
            float s = vsh[tt][p] + trsT[p * 65 + n];
            if (s > m) { m = s; bi = p; }
        }
        g_bp[(size_t)t * LBL + n] = (unsigned char)bi;
    }
}

// ---------------------------------------------------------------------------
// Phase 3a: per-chunk composed backpointer maps (64-entry byte maps).
// ---------------------------------------------------------------------------
__global__ void __launch_bounds__(64)
maps_kernel(int T, int K)
{
    __shared__ unsigned char sbp[S_CH * LBL];
    const int c = blockIdx.x, tid = threadIdx.x;
    const int lo = c * S_CH + 1;
    const int hi = min((c + 1) * S_CH, T - 1);
    const int nrows = hi - lo + 1;

    const uint4* src = reinterpret_cast<const uint4*>(g_bp + (size_t)lo * LBL);
    uint4* dst = reinterpret_cast<uint4*>(sbp);
    for (int i = tid; i < nrows * 4; i += 64) dst[i] = src[i];
    __syncthreads();

    int m = tid;
    for (int j = nrows - 1; j >= 0; j--) m = sbp[j * LBL + m];
    g_H[c * LBL + tid] = (unsigned char)m;
}

// ---------------------------------------------------------------------------
// Phase 3b: terminal argmax + score, then serial chase over K chunk maps.
// ---------------------------------------------------------------------------
__global__ void __launch_bounds__(64)
chase_kernel(const float* __restrict__ trans, int T, int K,
             float* __restrict__ out, int out_size)
{
    __shared__ unsigned char sh[MAXK * LBL];
    const int tid = threadIdx.x;
    for (int i = tid; i < K * 4; i += 64)
        reinterpret_cast<uint4*>(sh)[i] = reinterpret_cast<const uint4*>(g_H)[i];
    __syncthreads();

    if (tid == 0) {
        // terminal = V[T] + transitions[STOP]; STOP = 63
        float m = -3.4e38f; int best = 0;
        for (int p = 0; p < 64; p++) {
            float s = g_v[(size_t)(T - 1) * LBL + p] + trans[63 * 64 + p];
            if (s > m) { m = s; best = p; }
        }
        if (out_size > T) out[0] = m;   // path_score
        g_best = best;
        int e = best;                   // = path[T-1]
        for (int c = K - 1; c >= 1; c--) {
            e = sh[c * LBL + e];        // -> path[c*S]
            g_E[c] = e;
        }
    }
}

// ---------------------------------------------------------------------------
// Phase 3c: parallel fill. Chunk c writes path[j] for j in [c*S, hi).
// ---------------------------------------------------------------------------
__global__ void __launch_bounds__(64)
fill_kernel(int T, int K, float* __restrict__ out, int base)
{
    __shared__ unsigned char sbp[S_CH * LBL];
    const int c = blockIdx.x, tid = threadIdx.x;
    const int lo = c * S_CH + 1;
    const int hi = min((c + 1) * S_CH, T - 1);
    const int nrows = hi - lo + 1;

    const uint4* src = reinterpret_cast<const uint4*>(g_bp + (size_t)lo * LBL);
    uint4* dst = reinterpret_cast<uint4*>(sbp);
    for (int i = tid; i < nrows * 4; i += 64) dst[i] = src[i];
    __syncthreads();

    if (tid == 0) {
        int j, cur;
        if (c == K - 1) {
            cur = g_best;                       // path[T-1]
            out[base + T - 1] = (float)cur;
            j = T - 2;
        } else {
            const int x = g_E[c + 1];           // path[(c+1)*S]
            cur = sbp[(hi - lo) * LBL + x];     // bp[(c+1)*S][x] = path[hi-1]
            out[base + hi - 1] = (float)cur;
            j = hi - 2;
        }
        for (; j >= c * S_CH; j--) {
            cur = sbp[(j + 1 - lo) * LBL + cur];
            out[base + j] = (float)cur;
        }
    }
}

// ---------------------------------------------------------------------------
extern "C" void kernel_launch(void* const* d_in, const int* in_sizes, int n_in,
                              void* d_out, int out_size)
{
    const float* feats = (const float*)d_in[0];   // (1, T, 64) float32
    const float* trans = (const float*)d_in[1];   // (64, 64) float32
    float* out = (float*)d_out;

    const int T = in_sizes[0] / LBL;
    const int K = (T + S_CH - 1) / S_CH;
    const int base = (out_size > T) ? 1 : 0;

    fwd_kernel<<<1, 128>>>(feats, trans, T);

    const int nb = (T - 1 + 15) / 16;
    bp_kernel<<<nb, 256>>>(trans, T);

    maps_kernel<<<K, 64>>>(T, K);
    chase_kernel<<<1, 64>>>(trans, T, K, out, out_size);
    fill_kernel<<<K, 64>>>(T, K, out, base);
}

// round 17
// speedup vs baseline: 1.0163x; 1.0155x over previous
#include <cuda_runtime.h>

#define LBL   64
#define MAXT  200000
#define S_CH  500
#define MAXK  512
#define CSTEP 128                       // steps per feat chunk (R17: 64 -> 128)
#define CBYTES (CSTEP * LBL * 4)        // 32KB per buffer

// scratch (static device globals — no allocation)
__device__ float         g_v[(size_t)MAXT * LBL];   // g_v[t] = V[t+1] (v AFTER step t)
__device__ unsigned char g_bp[(size_t)MAXT * LBL];  // bp rows, row 0 unused
__device__ unsigned char g_H[MAXK * LBL];           // per-chunk composed maps
__device__ int           g_E[MAXK + 2];             // boundary path values
__device__ int           g_best;

// ---------------------------------------------------------------------------
// Phase 1: serial Viterbi forward pass (R14 body, best measured 21073.7us).
// 1 block, 128 threads (4 warps, 1 per SMSP). warp w handles tags
// n = 16w..16w+15; 2 lanes per tag (q=0,1), 32 prevs/lane.
// v row layout (176 floats):
//   [0..63]    primary v[0..63]
//   [80..111]  park slots (written by q=1 lanes of tags 0..31, never read)
//   [144..175] REPLICA of v[32..63], natural order (read by q=1)
// LDS (per chunk j): q=0 -> bank quad j, q=1 -> quad (4+j)&7 => disjoint,
// 1 wavefront per LDS.128 (the -5.8ms win of R10). STS per warp hits 32
// distinct banks => 1 wavefront. Chain: LDS -> add/max tree -> +feat ->
// 1 SHFL -> FMNMX -> STS -> BAR(nw=4, defer-blocking). Emission folded
// pre-shuffle (bit-exact: fmax(a+f,b+f)==fmax(a,b)+f). Step loop unroll 8.
// R17 change (single variable): feat chunk 64 -> 128 steps (halves the
// per-chunk wait/barrier/prefetch overhead, ~1.3 cyc/step). fsh moves to
// dynamic smem (2x32KB > 48KB static limit). Step-loop body IDENTICAL.
// Tested-and-rejected (do not reapply): full-64 unroll (R5), feat
// pipelining / batched stores (R6), add.rn.f32x2 (R7), dual-copy-v (R8),
// smem v-history copy-out (R12), post-barrier STG (R15).
// ---------------------------------------------------------------------------
__global__ void __launch_bounds__(128, 1)
fwd_kernel(const float* __restrict__ feats, const float* __restrict__ trans, int T)
{
    __shared__ __align__(16) float sv[2][176];
    extern __shared__ __align__(16) float fsh[];   // 2 x 32KB feat chunks (dynamic)

    const int tid  = threadIdx.x;
    const int w    = tid >> 5;
    const int lane = tid & 31;
    const int k    = lane >> 1;       // tag within warp (0..15)
    const int q    = lane & 1;        // prev-half (0: v[0..31], 1: v[32..63] via replica)
    const int n    = w * 16 + k;

    // transition segment T[n][q*32 .. q*32+31] (natural order)
    const float4* trr = reinterpret_cast<const float4*>(trans + n * 64 + q * 32);
    const float4 t0 = trr[0], t1 = trr[1], t2 = trr[2], t3 = trr[3];
    const float4 t4 = trr[4], t5 = trr[5], t6 = trr[6], t7 = trr[7];

    // init primary [0..63] and replica [144..175] (parks never read)
    if (tid < 64) {
        sv[0][tid] = (tid == 62) ? 0.0f : -10000.0f;           // START=62
    } else if (tid < 96) {
        sv[0][tid + 80] = ((tid - 32) == 62) ? 0.0f : -10000.0f; // replica of v[32..63]
    }

    const int nch = (T + CSTEP - 1) / CSTEP;
    const int totElems = T * LBL;
    const int rbase = q ? 144 : 0;                  // per-lane read base (floats)
    const int sbase = q ? ((n < 32) ? (80 + n) : (112 + n)) : n;  // store slot

    // prefetch one 32KB chunk (128 steps) with cp.async
    auto prefetch = [&](int ch, int buf) {
        const float* src = feats + (size_t)ch * (CSTEP * LBL);
        float* dst = fsh + buf * (CSTEP * LBL);
#pragma unroll
        for (int i = 0; i < CSTEP * LBL / 512; i++) {   // 16 iters of 16B x 128 thr
            int e = tid + i * 128;                      // 16B units within chunk
            if (ch * (CSTEP * LBL) + e * 4 + 3 < totElems) {
                unsigned saddr = (unsigned)__cvta_generic_to_shared(dst + e * 4);
                asm volatile("cp.async.cg.shared.global [%0], [%1], 16;"
                             :: "r"(saddr), "l"(src + e * 4));
            }
        }
        asm volatile("cp.async.commit_group;" ::: "memory");
    };

    prefetch(0, 0);
    if (nch > 1) prefetch(1, 1); else asm volatile("cp.async.commit_group;" ::: "memory");
    __syncthreads();

    for (int ch = 0; ch < nch; ch++) {
        asm volatile("cp.async.wait_group 1;" ::: "memory");
        __syncthreads();
        const float* fb  = fsh + (ch & 1) * (CSTEP * LBL) + n;       // imm offsets
        float*       gvp = g_v + (size_t)ch * (CSTEP * LBL) + n;     // imm offsets
        const int steps = min(CSTEP, T - ch * CSTEP);
#pragma unroll 8
        for (int i = 0; i < steps; i++) {
            const int cur = i & 1;  // compile-time under unroll-8
            const float4* vv = reinterpret_cast<const float4*>(&sv[cur][rbase]);
            const float4 a0 = vv[0], a1 = vv[1], a2 = vv[2], a3 = vv[3];
            const float4 a4 = vv[4], a5 = vv[5], a6 = vv[6], a7 = vv[7];
            float m0 = fmaxf(fmaxf(a0.x + t0.x, a0.y + t0.y), fmaxf(a0.z + t0.z, a0.w + t0.w));
            float m1 = fmaxf(fmaxf(a1.x + t1.x, a1.y + t1.y), fmaxf(a1.z + t1.z, a1.w + t1.w));
            float m2 = fmaxf(fmaxf(a2.x + t2.x, a2.y + t2.y), fmaxf(a2.z + t2.z, a2.w + t2.w));
            float m3 = fmaxf(fmaxf(a3.x + t3.x, a3.y + t3.y), fmaxf(a3.z + t3.z, a3.w + t3.w));
            float m4 = fmaxf(fmaxf(a4.x + t4.x, a4.y + t4.y), fmaxf(a4.z + t4.z, a4.w + t4.w));
            float m5 = fmaxf(fmaxf(a5.x + t5.x, a5.y + t5.y), fmaxf(a5.z + t5.z, a5.w + t5.w));
            float m6 = fmaxf(fmaxf(a6.x + t6.x, a6.y + t6.y), fmaxf(a6.z + t6.z, a6.w + t6.w));
            float m7 = fmaxf(fmaxf(a7.x + t7.x, a7.y + t7.y), fmaxf(a7.z + t7.z, a7.w + t7.w));
            float mm = fmaxf(fmaxf(fmaxf(m0, m1), fmaxf(m2, m3)),
                             fmaxf(fmaxf(m4, m5), fmaxf(m6, m7)));
            // fold emission before the shuffle (bit-exact, see header comment)
            mm += fb[i << 6];
            const float other = __shfl_xor_sync(0xffffffffu, mm, 1);
            const float vn = fmaxf(mm, other);
            sv[cur ^ 1][sbase] = vn;           // chain store (primary/park/replica)
            if (q == 1) gvp[i * LBL] = vn;     // off-chain store (global)
            __syncthreads();
        }
        if (ch + 2 < nch) prefetch(ch + 2, ch & 1);
        else asm volatile("cp.async.commit_group;" ::: "memory");
    }
}

// ---------------------------------------------------------------------------
// Phase 2: recompute backpointers for all t in [1, T-1], fully parallel.
// block handles 16 consecutive t (4 at a time); thread = (tt, n). Strict '>'
// ascending p == jnp.argmax first-index tie-break. Bit-exact adds.
// ---------------------------------------------------------------------------
__global__ void __launch_bounds__(256)
bp_kernel(const float* __restrict__ trans, int T)
{
    __shared__ float trsT[64 * 65];   // transposed + padded: trsT[p*65+n]
    __shared__ float vsh[4][64];

    const int tid = threadIdx.x;
    for (int x = tid; x < 4096; x += 256) {
        int nn = x >> 6, pp = x & 63;
        trsT[pp * 65 + nn] = trans[x];
    }
    const int base_t = 1 + blockIdx.x * 16;
    const int tt = tid >> 6, n = tid & 63;

    for (int r = 0; r < 4; r++) {
        const int t = base_t + r * 4 + tt;
        __syncthreads();
        if (t <= T - 1) vsh[tt][n] = g_v[(size_t)(t - 1) * LBL + n];  // = V[t]
        __syncthreads();
        if (t > T - 1) continue;

        float m = -3.4e38f;
        int bi = 0;
#pragma unroll 8
        for (int p = 0; p < 64; p++) {
            float s = vsh[tt][p] + trsT[p * 65 + n];
            if (s > m) { m = s; bi = p; }
        }
        g_bp[(size_t)t * LBL + n] = (unsigned char)bi;
    }
}

// ---------------------------------------------------------------------------
// Phase 3a: per-chunk composed backpointer maps (64-entry byte maps).
// ---------------------------------------------------------------------------
__global__ void __launch_bounds__(64)
maps_kernel(int T, int K)
{
    __shared__ unsigned char sbp[S_CH * LBL];
    const int c = blockIdx.x, tid = threadIdx.x;
    const int lo = c * S_CH + 1;
    const int hi = min((c + 1) * S_CH, T - 1);
    const int nrows = hi - lo + 1;

    const uint4* src = reinterpret_cast<const uint4*>(g_bp + (size_t)lo * LBL);
    uint4* dst = reinterpret_cast<uint4*>(sbp);
    for (int i = tid; i < nrows * 4; i += 64) dst[i] = src[i];
    __syncthreads();

    int m = tid;
    for (int j = nrows - 1; j >= 0; j--) m = sbp[j * LBL + m];
    g_H[c * LBL + tid] = (unsigned char)m;
}

// ---------------------------------------------------------------------------
// Phase 3b: terminal argmax + score, then serial chase over K chunk maps.
// ---------------------------------------------------------------------------
__global__ void __launch_bounds__(64)
chase_kernel(const float* __restrict__ trans, int T, int K,
             float* __restrict__ out, int out_size)
{
    __shared__ unsigned char sh[MAXK * LBL];
    const int tid = threadIdx.x;
    for (int i = tid; i < K * 4; i += 64)
        reinterpret_cast<uint4*>(sh)[i] = reinterpret_cast<const uint4*>(g_H)[i];
    __syncthreads();

    if (tid == 0) {
        // terminal = V[T] + transitions[STOP]; STOP = 63
        float m = -3.4e38f; int best = 0;
        for (int p = 0; p < 64; p++) {
            float s = g_v[(size_t)(T - 1) * LBL + p] + trans[63 * 64 + p];
            if (s > m) { m = s; best = p; }
        }
        if (out_size > T) out[0] = m;   // path_score
        g_best = best;
        int e = best;                   // = path[T-1]
        for (int c = K - 1; c >= 1; c--) {
            e = sh[c * LBL + e];        // -> path[c*S]
            g_E[c] = e;
        }
    }
}

// ---------------------------------------------------------------------------
// Phase 3c: parallel fill. Chunk c writes path[j] for j in [c*S, hi).
// ---------------------------------------------------------------------------
__global__ void __launch_bounds__(64)
fill_kernel(int T, int K, float* __restrict__ out, int base)
{
    __shared__ unsigned char sbp[S_CH * LBL];
    const int c = blockIdx.x, tid = threadIdx.x;
    const int lo = c * S_CH + 1;
    const int hi = min((c + 1) * S_CH, T - 1);
    const int nrows = hi - lo + 1;

    const uint4* src = reinterpret_cast<const uint4*>(g_bp + (size_t)lo * LBL);
    uint4* dst = reinterpret_cast<uint4*>(sbp);
    for (int i = tid; i < nrows * 4; i += 64) dst[i] = src[i];
    __syncthreads();

    if (tid == 0) {
        int j, cur;
        if (c == K - 1) {
            cur = g_best;                       // path[T-1]
            out[base + T - 1] = (float)cur;
            j = T - 2;
        } else {
            const int x = g_E[c + 1];           // path[(c+1)*S]
            cur = sbp[(hi - lo) * LBL + x];     // bp[(c+1)*S][x] = path[hi-1]
            out[base + hi - 1] = (float)cur;
            j = hi - 2;
        }
        for (; j >= c * S_CH; j--) {
            cur = sbp[(j + 1 - lo) * LBL + cur];
            out[base + j] = (float)cur;
        }
    }
}

// ---------------------------------------------------------------------------
extern "C" void kernel_launch(void* const* d_in, const int* in_sizes, int n_in,
                              void* d_out, int out_size)
{
    const float* feats = (const float*)d_in[0];   // (1, T, 64) float32
    const float* trans = (const float*)d_in[1];   // (64, 64) float32
    float* out = (float*)d_out;

    const int T = in_sizes[0] / LBL;
    const int K = (T + S_CH - 1) / S_CH;
    const int base = (out_size > T) ? 1 : 0;

    // opt-in for 64KB dynamic smem (2 x 32KB feat buffers); idempotent, no alloc
    static int attr_done = 0;
    if (!attr_done) {
        cudaFuncSetAttribute(fwd_kernel,
                             cudaFuncAttributeMaxDynamicSharedMemorySize, 2 * CBYTES);
        attr_done = 1;
    }

    fwd_kernel<<<1, 128, 2 * CBYTES>>>(feats, trans, T);

    const int nb = (T - 1 + 15) / 16;
    bp_kernel<<<nb, 256>>>(trans, T);

    maps_kernel<<<K, 64>>>(T, K);
    chase_kernel<<<1, 64>>>(trans, T, K, out, out_size);
    fill_kernel<<<K, 64>>>(T, K, out, base);
}